// round 13
// baseline (speedup 1.0000x reference)
#include <cuda_runtime.h>
#include <cuda_bf16.h>

// TTTConv: causal depthwise conv1d (fused conv_output + conv_states)
//   x: (B,N,D) fp32, w: (D,K), bias: (D,);  B=4, N=4096, D=2048, K=4
// d_out = [ conv_output (B,N,D) | conv_states (B,D,K) ]
//
// Software-pipelined variant: double-buffered CH=2 chunks keep loads
// continuously in flight (load c+1 -> compute/store c -> swap) at the same
// 16-register buffer footprint as the previous buf[4] scheme. regs<=64,
// 4 CTAs/SM.

#define Bc 4
#define Nc 4096
#define Dc 2048
#define Kc 4
#define NT 32          // time steps per thread
#define CH 2           // pipeline stage depth (2 loads per stage)
#define DV (Dc / 4)    // float4 groups along D = 512

__global__ void __launch_bounds__(256, 4) ttt_conv_fused(
    const float* __restrict__ x,
    const float* __restrict__ w,
    const float* __restrict__ bias,
    float* __restrict__ out,
    float* __restrict__ states)
{
    int tid  = blockIdx.x * blockDim.x + threadIdx.x;
    int dvec = tid % DV;                 // float4 group along D
    int nt   = (tid / DV) % (Nc / NT);   // time tile
    int b    = tid / (DV * (Nc / NT));   // batch
    int d    = dvec * 4;
    int n0   = nt * NT;

    float4 wv0 = ((const float4*)w)[d + 0];
    float4 wv1 = ((const float4*)w)[d + 1];
    float4 wv2 = ((const float4*)w)[d + 2];
    float4 wv3 = ((const float4*)w)[d + 3];
    float4 bv  = ((const float4*)bias)[dvec];

    // 32-bit byte offsets (tensors << 4GB): base points at (b, n0, d)
    unsigned base = ((unsigned)b * Nc * Dc + (unsigned)n0 * Dc + (unsigned)d) * 4u;
    const char* xp = (const char*)x   + base;
    char*       op = (char*)      out + base;
    const unsigned ROW = Dc * 4u;  // byte stride per time step

    // Sliding window: x at n-3, n-2, n-1
    float4 xm3, xm2, xm1;
    if (n0 == 0) {
        xm3 = make_float4(0.f, 0.f, 0.f, 0.f);
        xm2 = xm3;
        xm1 = xm3;
    } else {
        xm3 = *(const float4*)(xp - 3 * ROW);
        xm2 = *(const float4*)(xp - 2 * ROW);
        xm1 = *(const float4*)(xp - 1 * ROW);
    }

    // Prologue: load stage 0
    float4 bufA0 = *(const float4*)(xp + 0u * ROW);
    float4 bufA1 = *(const float4*)(xp + 1u * ROW);

#pragma unroll
    for (int c = 0; c < NT / CH; ++c) {
        // ---- issue next stage's loads before consuming current stage ----
        float4 bufB0, bufB1;
        if (c + 1 < NT / CH) {
            bufB0 = *(const float4*)(xp + (unsigned)((c + 1) * CH + 0) * ROW);
            bufB1 = *(const float4*)(xp + (unsigned)((c + 1) * CH + 1) * ROW);
        }

        // ---- compute + store current stage ----
#pragma unroll
        for (int i = 0; i < CH; ++i) {
            float4 xc = (i == 0) ? bufA0 : bufA1;
            float4 r;
            r.x = fmaf(xm3.x, wv0.x, fmaf(xm2.x, wv0.y, fmaf(xm1.x, wv0.z, fmaf(xc.x, wv0.w, bv.x))));
            r.y = fmaf(xm3.y, wv1.x, fmaf(xm2.y, wv1.y, fmaf(xm1.y, wv1.z, fmaf(xc.y, wv1.w, bv.y))));
            r.z = fmaf(xm3.z, wv2.x, fmaf(xm2.z, wv2.y, fmaf(xm1.z, wv2.z, fmaf(xc.z, wv2.w, bv.z))));
            r.w = fmaf(xm3.w, wv3.x, fmaf(xm2.w, wv3.y, fmaf(xm1.w, wv3.z, fmaf(xc.w, wv3.w, bv.w))));
            *(float4*)(op + (unsigned)(c * CH + i) * ROW) = r;
            xm3 = xm2; xm2 = xm1; xm1 = xc;
        }

        bufA0 = bufB0;
        bufA1 = bufB1;
    }

    // Last time-tile threads emit conv_states (B, D, K): k contiguous ->
    // one float4 per channel. Window regs hold x[N-3..N-1]; reload x[N-4]
    // (L2 hit — just streamed by this thread).
    if (n0 == Nc - NT) {
        float4 a = *(const float4*)(xp + (unsigned)(NT - 4) * ROW);
        float4* sb = (float4*)states + (size_t)b * Dc + d;
        sb[0] = make_float4(a.x, xm3.x, xm2.x, xm1.x);
        sb[1] = make_float4(a.y, xm3.y, xm2.y, xm1.y);
        sb[2] = make_float4(a.z, xm3.z, xm2.z, xm1.z);
        sb[3] = make_float4(a.w, xm3.w, xm2.w, xm1.w);
    }
}

extern "C" void kernel_launch(void* const* d_in, const int* in_sizes, int n_in,
                              void* d_out, int out_size)
{
    const float* x    = (const float*)d_in[0];
    const float* w    = (const float*)d_in[1];
    const float* bias = (const float*)d_in[2];
    float* out    = (float*)d_out;
    float* states = out + (size_t)Bc * Nc * Dc;

    int total = Bc * (Nc / NT) * DV;   // 262144 threads -> 1024 blocks
    ttt_conv_fused<<<total / 256, 256>>>(x, w, bias, out, states);
}

// round 15
// speedup vs baseline: 1.0047x; 1.0047x over previous
#include <cuda_runtime.h>
#include <cuda_bf16.h>

// TTTConv: causal depthwise conv1d (fused conv_output + conv_states)
//   x: (B,N,D) fp32, w: (D,K), bias: (D,);  B=4, N=4096, D=2048, K=4
// d_out = [ conv_output (B,N,D) | conv_states (B,D,K) ]
//
// FINAL (champion R12 config): per-thread sliding window along N over 4
// consecutive channels (float4), CH=4 front-batched LDG.128 per chunk,
// inline stores, 4 CTAs/SM (regs=64). Measured kernel 38.1us = 6.7 TB/s
// effective DRAM (~84% of spec) — the practical mixed read/write HBM
// ceiling. Invariant across 8 structural variants (R4-R13).

#define Bc 4
#define Nc 4096
#define Dc 2048
#define Kc 4
#define NT 32          // time steps per thread
#define CH 4           // chunk: loads batched 4-deep for MLP
#define DV (Dc / 4)    // float4 groups along D = 512

__global__ void __launch_bounds__(256, 4) ttt_conv_fused(
    const float* __restrict__ x,
    const float* __restrict__ w,
    const float* __restrict__ bias,
    float* __restrict__ out,
    float* __restrict__ states)
{
    int tid  = blockIdx.x * blockDim.x + threadIdx.x;
    int dvec = tid % DV;                 // float4 group along D
    int nt   = (tid / DV) % (Nc / NT);   // time tile
    int b    = tid / (DV * (Nc / NT));   // batch
    int d    = dvec * 4;
    int n0   = nt * NT;

    float4 wv0 = ((const float4*)w)[d + 0];
    float4 wv1 = ((const float4*)w)[d + 1];
    float4 wv2 = ((const float4*)w)[d + 2];
    float4 wv3 = ((const float4*)w)[d + 3];
    float4 bv  = ((const float4*)bias)[dvec];

    // 32-bit byte offsets (tensors << 4GB): base points at (b, n0, d)
    unsigned base = ((unsigned)b * Nc * Dc + (unsigned)n0 * Dc + (unsigned)d) * 4u;
    const char* xp = (const char*)x   + base;
    char*       op = (char*)      out + base;
    const unsigned ROW = Dc * 4u;  // byte stride per time step

    // Sliding window: x at n-3, n-2, n-1
    float4 xm3, xm2, xm1;
    if (n0 == 0) {
        xm3 = make_float4(0.f, 0.f, 0.f, 0.f);
        xm2 = xm3;
        xm1 = xm3;
    } else {
        xm3 = *(const float4*)(xp - 3 * ROW);
        xm2 = *(const float4*)(xp - 2 * ROW);
        xm1 = *(const float4*)(xp - 1 * ROW);
    }

#pragma unroll
    for (int c = 0; c < NT / CH; ++c) {
        // ---- batch loads: CH independent LDG.128 front-to-front ----
        float4 buf[CH];
#pragma unroll
        for (int i = 0; i < CH; ++i)
            buf[i] = *(const float4*)(xp + (unsigned)(c * CH + i) * ROW);

        // ---- compute + store inline (stores are fire-and-forget) ----
#pragma unroll
        for (int i = 0; i < CH; ++i) {
            float4 xc = buf[i];
            float4 r;
            r.x = fmaf(xm3.x, wv0.x, fmaf(xm2.x, wv0.y, fmaf(xm1.x, wv0.z, fmaf(xc.x, wv0.w, bv.x))));
            r.y = fmaf(xm3.y, wv1.x, fmaf(xm2.y, wv1.y, fmaf(xm1.y, wv1.z, fmaf(xc.y, wv1.w, bv.y))));
            r.z = fmaf(xm3.z, wv2.x, fmaf(xm2.z, wv2.y, fmaf(xm1.z, wv2.z, fmaf(xc.z, wv2.w, bv.z))));
            r.w = fmaf(xm3.w, wv3.x, fmaf(xm2.w, wv3.y, fmaf(xm1.w, wv3.z, fmaf(xc.w, wv3.w, bv.w))));
            *(float4*)(op + (unsigned)(c * CH + i) * ROW) = r;
            xm3 = xm2; xm2 = xm1; xm1 = xc;
        }
    }

    // Last time-tile threads emit conv_states (B, D, K): k contiguous ->
    // one float4 per channel. Window regs hold x[N-3..N-1]; reload x[N-4]
    // (L2 hit — just streamed by this thread).
    if (n0 == Nc - NT) {
        float4 a = *(const float4*)(xp + (unsigned)(NT - 4) * ROW);
        float4* sb = (float4*)states + (size_t)b * Dc + d;
        sb[0] = make_float4(a.x, xm3.x, xm2.x, xm1.x);
        sb[1] = make_float4(a.y, xm3.y, xm2.y, xm1.y);
        sb[2] = make_float4(a.z, xm3.z, xm2.z, xm1.z);
        sb[3] = make_float4(a.w, xm3.w, xm2.w, xm1.w);
    }
}

extern "C" void kernel_launch(void* const* d_in, const int* in_sizes, int n_in,
                              void* d_out, int out_size)
{
    const float* x    = (const float*)d_in[0];
    const float* w    = (const float*)d_in[1];
    const float* bias = (const float*)d_in[2];
    float* out    = (float*)d_out;
    float* states = out + (size_t)Bc * Nc * Dc;

    int total = Bc * (Nc / NT) * DV;   // 262144 threads -> 1024 blocks
    ttt_conv_fused<<<total / 256, 256>>>(x, w, bias, out, states);
}